// round 11
// baseline (speedup 1.0000x reference)
#include <cuda_runtime.h>
#include <cuda_fp16.h>
#include <cstdint>

typedef unsigned long long ull;

#define BMAX 32768

// ---------------- scratch (static device globals: no allocation) ----------------
__device__ __align__(16) float g_rot[18 * 8];
__device__ __align__(16) __half g_af[(size_t)BMAX * 128];  // A (activations) fp16
__device__ __align__(16) __half g_bh[1296 * 128];          // w2^T fp16 [N,K]
__device__ __align__(16) __half g_w1p[32 * 32 * 4 * 8];    // enc_w1 packed frags hi/lo

// ---------------- f32x2 packed helpers ----------------
__device__ __forceinline__ ull f2pack(float a, float b) {
    ull r;
    asm("mov.b64 %0, {%1, %2};" : "=l"(r) : "r"(__float_as_uint(a)), "r"(__float_as_uint(b)));
    return r;
}
__device__ __forceinline__ void f2unpack(ull v, float& a, float& b) {
    unsigned int lo, hi;
    asm("mov.b64 {%0, %1}, %2;" : "=r"(lo), "=r"(hi) : "l"(v));
    a = __uint_as_float(lo); b = __uint_as_float(hi);
}
__device__ __forceinline__ ull ffma2(ull a, ull b, ull c) {
    ull d;
    asm("fma.rn.f32x2 %0, %1, %2, %3;" : "=l"(d) : "l"(a), "l"(b), "l"(c));
    return d;
}
__device__ __forceinline__ ull fmul2(ull a, ull b) {
    ull d;
    asm("mul.rn.f32x2 %0, %1, %2;" : "=l"(d) : "l"(a), "l"(b));
    return d;
}

// ---------------- mma/ldmatrix helpers ----------------
__device__ __forceinline__ uint32_t smem_u32(const void* p) {
    uint32_t a;
    asm("{ .reg .u64 t; cvta.to.shared.u64 t, %1; cvt.u32.u64 %0, t; }" : "=r"(a) : "l"(p));
    return a;
}
__device__ __forceinline__ void ldsm4(uint32_t& r0, uint32_t& r1, uint32_t& r2, uint32_t& r3,
                                      uint32_t a) {
    asm volatile("ldmatrix.sync.aligned.m8n8.x4.shared.b16 {%0,%1,%2,%3}, [%4];"
                 : "=r"(r0), "=r"(r1), "=r"(r2), "=r"(r3) : "r"(a));
}
__device__ __forceinline__ void mma16816(float* d, uint32_t a0, uint32_t a1, uint32_t a2,
                                         uint32_t a3, uint32_t b0, uint32_t b1) {
    asm volatile(
        "mma.sync.aligned.m16n8k16.row.col.f32.f16.f16.f32 "
        "{%0,%1,%2,%3}, {%4,%5,%6,%7}, {%8,%9}, {%0,%1,%2,%3};"
        : "+f"(d[0]), "+f"(d[1]), "+f"(d[2]), "+f"(d[3])
        : "r"(a0), "r"(a1), "r"(a2), "r"(a3), "r"(b0), "r"(b1));
}
__device__ __forceinline__ uint32_t smaddr(uint32_t base, int row, int c) {
    return base + row * 256 + (((uint32_t)(c ^ (row & 7))) << 4);
}
__device__ __forceinline__ uint32_t h2pack(float a, float b) {
    __half2 h = __floats2half2_rn(a, b);
    return *(uint32_t*)&h;
}

// ---------------- K0: precompute Rot matrices ----------------
__global__ void k0_rot(const float* __restrict__ qw) {
    int t = threadIdx.x;
    if (t >= 18) return;
    float phi = qw[t * 3 + 0], th = qw[t * 3 + 1], om = qw[t * 3 + 2];
    float c = cosf(th * 0.5f), s = sinf(th * 0.5f);
    float ap = -(phi + om) * 0.5f, am = -(phi - om) * 0.5f;
    float sp, cp, sm, cm;
    sincosf(ap, &sp, &cp);
    sincosf(am, &sm, &cm);
    float* r = g_rot + t * 8;
    r[0] = cp * c;  r[1] = sp * c;
    r[2] = -cm * s; r[3] = sm * s;
    r[4] = cm * s;  r[5] = sm * s;
    r[6] = cp * c;  r[7] = -sp * c;
}

// ---------------- K0b: transpose head_w2 [128,1296] -> fp16 [1296,128] ----------------
__global__ void k_w2split(const float* __restrict__ w2) {
    int i = blockIdx.x * blockDim.x + threadIdx.x;
    if (i >= 1296 * 128) return;
    int n = i >> 7, k = i & 127;
    g_bh[i] = __float2half_rn(w2[k * 1296 + n]);
}

// ---------------- K0c: pack enc_w1 into mma-fragment order, fp16 hi/lo ----
__global__ void k_w1pack(const float* __restrict__ w1) {
    int i = blockIdx.x * blockDim.x + threadIdx.x;
    if (i >= 4096) return;
    int q = i & 3, ks = (i >> 2) & 31, n = i >> 7;
    int kc = ks * 16 + 4 * q;
    float v0 = w1[(kc + 0) * 32 + n];
    float v1 = w1[(kc + 1) * 32 + n];
    float v2 = w1[(kc + 2) * 32 + n];
    float v3 = w1[(kc + 3) * 32 + n];
    __half h[8];
    h[0] = __float2half_rn(v0); h[1] = __float2half_rn(v1);
    h[2] = __float2half_rn(v2); h[3] = __float2half_rn(v3);
    h[4] = __float2half_rn(v0 - __half2float(h[0]));
    h[5] = __float2half_rn(v1 - __half2float(h[1]));
    h[6] = __float2half_rn(v2 - __half2float(h[2]));
    h[7] = __float2half_rn(v3 - __half2float(h[3]));
    *(uint4*)(g_w1p + (size_t)i * 8) = *(uint4*)h;
}

// ---------------- circuit helpers ----------------
__device__ __forceinline__ float2 shflx(float2 v, int m) {
    float2 r;
    r.x = __shfl_xor_sync(0xffffffffu, v.x, m);
    r.y = __shfl_xor_sync(0xffffffffu, v.y, m);
    return r;
}
__device__ __forceinline__ float2 cmul(float2 a, float2 b) {
    return make_float2(a.x * b.x - a.y * b.y, a.x * b.y + a.y * b.x);
}
__device__ __forceinline__ float2 cmadd(float2 a, float2 b, float2 acc) {
    return make_float2(acc.x + a.x * b.x - a.y * b.y, acc.y + a.x * b.y + a.y * b.x);
}
__device__ __forceinline__ void swp(float2& a, float2& b) { float2 t = a; a = b; b = t; }

// ---------------- K12: fused encoder (HMMA) + circuit ----------------
// phase 1: 32 rows/CTA (2 tiles x 4 K-split warps)
// phase 2: 8 samples/warp, 4 lanes/sample, 16 amps/lane (warps 0-3)
//   amp a = (l2<<4)|j ; bit5=l2b1(q0), bit4=l2b0(q1), bits3..0=j(q2..q5)
__global__ __launch_bounds__(256)
void k12_fused(const float* __restrict__ x,
               const float* __restrict__ b1,
               const float* __restrict__ w2,
               const float* __restrict__ b2,
               const float* __restrict__ hw1,
               const float* __restrict__ hb1, int base) {
    __shared__ float red[2][3][32][16];
    __shared__ float sang[32][6];

    int tid = threadIdx.x, lane = tid & 31, wid = tid >> 5;

    // ======== phase 1: encoder ========
    {
        int tile = wid >> 2, tw = wid & 3;
        int m0 = base + blockIdx.x * 32 + tile * 16;
        int g = lane >> 2, q = lane & 3;
        const float* xr0 = x + (size_t)(m0 + g) * 512;
        const float* xr1 = x + (size_t)(m0 + g + 8) * 512;

        float acc[4][4];
#pragma unroll
        for (int nf = 0; nf < 4; nf++)
#pragma unroll
            for (int v = 0; v < 4; v++) acc[nf][v] = 0.f;

#pragma unroll
        for (int kk = 0; kk < 8; kk++) {
            int ks = tw * 8 + kk;
            int kc = ks * 16 + 4 * q;
            float4 v0 = *(const float4*)(xr0 + kc);
            float4 v1 = *(const float4*)(xr1 + kc);

            uint32_t ah0 = h2pack(v0.x, v0.y), ah1 = h2pack(v1.x, v1.y);
            uint32_t ah2 = h2pack(v0.z, v0.w), ah3 = h2pack(v1.z, v1.w);
            __half2 t0 = *(__half2*)&ah0, t1 = *(__half2*)&ah1;
            __half2 t2 = *(__half2*)&ah2, t3 = *(__half2*)&ah3;
            uint32_t al0 = h2pack(v0.x - __low2float(t0), v0.y - __high2float(t0));
            uint32_t al1 = h2pack(v1.x - __low2float(t1), v1.y - __high2float(t1));
            uint32_t al2 = h2pack(v0.z - __low2float(t2), v0.w - __high2float(t2));
            uint32_t al3 = h2pack(v1.z - __low2float(t3), v1.w - __high2float(t3));

#pragma unroll
            for (int nf = 0; nf < 4; nf++) {
                int n = nf * 8 + g;
                uint4 bv = *(const uint4*)(g_w1p + (size_t)(((n * 32 + ks) * 4 + q)) * 8);
                mma16816(acc[nf], ah0, ah1, ah2, ah3, bv.x, bv.y);
                mma16816(acc[nf], ah0, ah1, ah2, ah3, bv.z, bv.w);
                mma16816(acc[nf], al0, al1, al2, al3, bv.x, bv.y);
            }
        }

        if (tw) {
            float4* dst = (float4*)red[tile][tw - 1][lane];
#pragma unroll
            for (int nf = 0; nf < 4; nf++) dst[nf] = *(float4*)acc[nf];
        }
        __syncthreads();

        if (tw == 0) {
#pragma unroll
            for (int w = 0; w < 3; w++) {
                const float* src = red[tile][w][lane];
#pragma unroll
                for (int nf = 0; nf < 4; nf++)
#pragma unroll
                    for (int v = 0; v < 4; v++) acc[nf][v] += src[nf * 4 + v];
            }

            float pr0[6], pr1[6];
#pragma unroll
            for (int i = 0; i < 6; i++) { pr0[i] = 0.f; pr1[i] = 0.f; }

#pragma unroll
            for (int nf = 0; nf < 4; nf++) {
                int c0 = nf * 8 + 2 * q;
                float bb0 = b1[c0], bb1 = b1[c0 + 1];
                float h00 = tanhf(acc[nf][0] + bb0);
                float h01 = tanhf(acc[nf][1] + bb1);
                float h10 = tanhf(acc[nf][2] + bb0);
                float h11 = tanhf(acc[nf][3] + bb1);
#pragma unroll
                for (int i = 0; i < 6; i++) {
                    float w0 = w2[c0 * 6 + i], w1v = w2[(c0 + 1) * 6 + i];
                    pr0[i] += h00 * w0 + h01 * w1v;
                    pr1[i] += h10 * w0 + h11 * w1v;
                }
            }
#pragma unroll
            for (int m = 1; m <= 2; m <<= 1) {
#pragma unroll
                for (int i = 0; i < 6; i++) {
                    pr0[i] += __shfl_xor_sync(0xffffffffu, pr0[i], m);
                    pr1[i] += __shfl_xor_sync(0xffffffffu, pr1[i], m);
                }
            }
            if (q == 0) {
#pragma unroll
                for (int i = 0; i < 6; i++) {
                    sang[tile * 16 + g][i] = pr0[i] + b2[i];
                    sang[tile * 16 + g + 8][i] = pr1[i] + b2[i];
                }
            }
        }
    }
    __syncthreads();

    // ======== phase 2: circuit (warps 0-3; 8 samples/warp) ========
    if (wid >= 4) return;
    int l2 = lane & 3;
    int ls = wid * 8 + (lane >> 2);
    int s = base + blockIdx.x * 32 + ls;

    float cs[6], sn[6];
#pragma unroll
    for (int q = 0; q < 6; q++) {
        float a = sang[ls][q];
        __sincosf(0.5f * a, &sn[q], &cs[q]);
    }

    float2 A[16];
#pragma unroll
    for (int j = 0; j < 16; j++) A[j] = make_float2(0.f, 0.f);
    if (l2 == 0) A[0].x = 1.f;

#pragma unroll
    for (int L = 0; L < 3; L++) {
#pragma unroll
        for (int q = 0; q < 6; q++) {
            const ull* up = (const ull*)(g_rot + (L * 6 + q) * 8);
            ull u01 = up[0], u23 = up[1], u45 = up[2], u67 = up[3];
            float c = cs[q], s2 = sn[q];
            ull cp = f2pack(c, c), sp = f2pack(s2, s2), sn2 = f2pack(-s2, -s2);
            float2 f00, f01, f10, f11;
            f2unpack(ffma2(u23, sp, fmul2(u01, cp)), f00.x, f00.y);
            f2unpack(ffma2(u01, sn2, fmul2(u23, cp)), f01.x, f01.y);
            f2unpack(ffma2(u67, sp, fmul2(u45, cp)), f10.x, f10.y);
            f2unpack(ffma2(u45, sn2, fmul2(u67, cp)), f11.x, f11.y);

            if (q <= 1) {
                int m = 2 >> q;  // q0->2, q1->1
                bool hi = (l2 & m) != 0;
                float2 ua = hi ? f11 : f00;
                float2 ub = hi ? f10 : f01;
#pragma unroll
                for (int j = 0; j < 16; j++) {
                    float2 P = shflx(A[j], m);
                    A[j] = cmadd(ub, P, cmul(ua, A[j]));
                }
            } else {
                int st = 1 << (5 - q);  // q2->8, q3->4, q4->2, q5->1
#pragma unroll
                for (int i0 = 0; i0 < 16; i0++) {
                    if (i0 & st) continue;
                    int i1 = i0 | st;
                    float2 n0 = cmadd(f01, A[i1], cmul(f00, A[i0]));
                    float2 n1 = cmadd(f11, A[i1], cmul(f10, A[i0]));
                    A[i0] = n0; A[i1] = n1;
                }
            }
        }
        // CNOT(0,1): ctrl l2b1, tgt l2b0
        {
#pragma unroll
            for (int j = 0; j < 16; j++) {
                float2 P = shflx(A[j], 1);
                if (l2 & 2) A[j] = P;
            }
        }
        // CNOT(2,3): ctrl j3, tgt j2
        swp(A[8], A[12]); swp(A[9], A[13]); swp(A[10], A[14]); swp(A[11], A[15]);
        // CNOT(4,5): ctrl j1, tgt j0
        swp(A[2], A[3]); swp(A[6], A[7]); swp(A[10], A[11]); swp(A[14], A[15]);
        // CNOT(1,2): ctrl l2b0, tgt j3
        if (l2 & 1) {
#pragma unroll
            for (int j = 0; j < 8; j++) swp(A[j], A[j + 8]);
        }
        // CNOT(3,4): ctrl j2, tgt j1
        swp(A[4], A[6]); swp(A[5], A[7]); swp(A[12], A[14]); swp(A[13], A[15]);
        // CNOT(5,0): ctrl j0, tgt l2b1
        {
            A[1] = shflx(A[1], 2);  A[3] = shflx(A[3], 2);
            A[5] = shflx(A[5], 2);  A[7] = shflx(A[7], 2);
            A[9] = shflx(A[9], 2);  A[11] = shflx(A[11], 2);
            A[13] = shflx(A[13], 2); A[15] = shflx(A[15], 2);
        }
    }

    float p[16];
#pragma unroll
    for (int j = 0; j < 16; j++) p[j] = A[j].x * A[j].x + A[j].y * A[j].y;
    float sum = 0.f;
#pragma unroll
    for (int j = 0; j < 16; j++) sum += p[j];
    float s3 = 0.f, s4 = 0.f, s5 = 0.f, s2h = 0.f;
#pragma unroll
    for (int j = 0; j < 16; j++) {
        if (j & 8) s2h += p[j];
        if (j & 4) s3 += p[j];
        if (j & 2) s4 += p[j];
        if (j & 1) s5 += p[j];
    }
    float z[6];
    z[0] = (l2 & 2) ? -sum : sum;
    z[1] = (l2 & 1) ? -sum : sum;
    z[2] = sum - 2.f * s2h;
    z[3] = sum - 2.f * s3;
    z[4] = sum - 2.f * s4;
    z[5] = sum - 2.f * s5;
#pragma unroll
    for (int off = 2; off; off >>= 1) {
#pragma unroll
        for (int q = 0; q < 6; q++) z[q] += __shfl_xor_sync(0xffffffffu, z[q], off);
    }

    // head layer 1: lane handles 32 outputs j = l2*32 .. +31
    __half hv[32];
#pragma unroll
    for (int u = 0; u < 32; u++) {
        int j = l2 * 32 + u;
        float a = hb1[j];
#pragma unroll
        for (int i = 0; i < 6; i++) a += z[i] * hw1[i * 128 + j];
        hv[u] = __float2half_rn(fmaxf(a, 0.f));
    }
    uint4* dst = (uint4*)(g_af + (size_t)s * 128 + l2 * 32);
    dst[0] = *(uint4*)&hv[0];
    dst[1] = *(uint4*)&hv[8];
    dst[2] = *(uint4*)&hv[16];
    dst[3] = *(uint4*)&hv[24];
}

// ---------------- K3: HMMA fp16 GEMM  out = A[B,128] @ w2[128,1296] + b2 ----
#define K3_SMEM (32768 + 36864)

__global__ __launch_bounds__(256, 2)
void k3_mma(const float* __restrict__ b2, float* __restrict__ out, int base) {
    extern __shared__ char sm3[];
    __half* sA  = (__half*)sm3;            // 128 x 128
    __half* sBh = (__half*)(sm3 + 32768);  // 144 x 128

    int tid = threadIdx.x, lane = tid & 31, wid = tid >> 5;
    int n0 = blockIdx.x * 144;
    int m0 = base + blockIdx.y * 128;

    const uint4* gA = (const uint4*)g_af + (size_t)m0 * 16;
    uint4* dA = (uint4*)sA;
#pragma unroll
    for (int it = 0; it < 8; it++) {
        int i = it * 256 + tid;
        int r = i >> 4, c = i & 15;
        dA[r * 16 + (c ^ (r & 7))] = gA[i];
    }
    const uint4* gBh = (const uint4*)g_bh + (size_t)n0 * 16;
    uint4* dBh = (uint4*)sBh;
#pragma unroll
    for (int it = 0; it < 9; it++) {
        int i = it * 256 + tid;
        int r = i >> 4, c = i & 15;
        dBh[r * 16 + (c ^ (r & 7))] = gBh[i];
    }
    __syncthreads();

    uint32_t sAb = smem_u32(sA), sBhb = smem_u32(sBh);
    int la = lane & 7, hb = (lane >> 3) & 1, hc = lane >> 4;
    int arow = wid * 16 + la + (hb << 3);
    int brow = la + (hb << 3);

    float acc[18][4];
#pragma unroll
    for (int j = 0; j < 18; j++)
#pragma unroll
        for (int v = 0; v < 4; v++) acc[j][v] = 0.f;

#pragma unroll
    for (int ks = 0; ks < 8; ks++) {
        int ca = 2 * ks + hc;
        uint32_t a0, a1, a2, a3;
        ldsm4(a0, a1, a2, a3, smaddr(sAb, arow, ca));

#pragma unroll
        for (int p = 0; p < 9; p++) {
            uint32_t r0, r1, r2, r3;
            ldsm4(r0, r1, r2, r3, smaddr(sBhb, p * 16 + brow, ca));
            mma16816(acc[2 * p],     a0, a1, a2, a3, r0, r2);
            mma16816(acc[2 * p + 1], a0, a1, a2, a3, r1, r3);
        }
    }

    int orow0 = m0 + wid * 16 + (lane >> 2);
    float* op = out + (size_t)orow0 * 1296 + n0 + 2 * (lane & 3);
    const float* bp = b2 + n0 + 2 * (lane & 3);
#pragma unroll
    for (int j = 0; j < 18; j++) {
        float2 bias = *(const float2*)(bp + 8 * j);
        float2 v0 = make_float2(acc[j][0] + bias.x, acc[j][1] + bias.y);
        float2 v1 = make_float2(acc[j][2] + bias.x, acc[j][3] + bias.y);
        __stcs((float2*)(op + 8 * j), v0);
        __stcs((float2*)(op + 8 * j + 8 * 1296), v1);
    }
}

// ---------------- launch: staggered 2-chunk pipeline (k12(c1) ∥ k3(c0)) ----------------
extern "C" void kernel_launch(void* const* d_in, const int* in_sizes, int n_in,
                              void* d_out, int out_size) {
    const float* x   = (const float*)d_in[0];
    const float* ew1 = (const float*)d_in[1];
    const float* eb1 = (const float*)d_in[2];
    const float* ew2 = (const float*)d_in[3];
    const float* eb2 = (const float*)d_in[4];
    const float* qw  = (const float*)d_in[5];
    const float* hw1 = (const float*)d_in[6];
    const float* hb1 = (const float*)d_in[7];
    const float* hw2 = (const float*)d_in[8];
    const float* hb2 = (const float*)d_in[9];
    float* out = (float*)d_out;

    int B = in_sizes[0] / 512;

    static bool inited = false;
    static cudaStream_t st[2];
    static cudaEvent_t evA, evJoin0, evJoin1;
    if (!inited) {
        cudaStreamCreateWithFlags(&st[0], cudaStreamNonBlocking);
        cudaStreamCreateWithFlags(&st[1], cudaStreamNonBlocking);
        cudaEventCreateWithFlags(&evA, cudaEventDisableTiming);
        cudaEventCreateWithFlags(&evJoin0, cudaEventDisableTiming);
        cudaEventCreateWithFlags(&evJoin1, cudaEventDisableTiming);
        cudaFuncSetAttribute(k3_mma, cudaFuncAttributeMaxDynamicSharedMemorySize, K3_SMEM);
        inited = true;
    }

    // prep (batch-invariant) on the capture (default) stream
    k0_rot<<<1, 32>>>(qw);
    k_w1pack<<<16, 256>>>(ew1);
    k_w2split<<<(1296 * 128 + 255) / 256, 256>>>(hw2);

    // fork to s0
    static cudaEvent_t evFork = nullptr;
    if (!evFork) cudaEventCreateWithFlags(&evFork, cudaEventDisableTiming);
    cudaEventRecord(evFork, 0);
    cudaStreamWaitEvent(st[0], evFork, 0);

    int chunk = B / 2;  // 16384
    // s0: k12(c0) -> evA -> k3(c0)
    k12_fused<<<chunk / 32, 256, 0, st[0]>>>(x, eb1, ew2, eb2, hw1, hb1, 0);
    cudaEventRecord(evA, st[0]);
    dim3 g3(9, chunk / 128);
    k3_mma<<<g3, 256, K3_SMEM, st[0]>>>(hb2, out, 0);

    // s1: wait k12(c0) -> k12(c1) -> k3(c1)   [k12(c1) co-runs with k3(c0)]
    cudaStreamWaitEvent(st[1], evA, 0);
    k12_fused<<<chunk / 32, 256, 0, st[1]>>>(x, eb1, ew2, eb2, hw1, hb1, chunk);
    k3_mma<<<g3, 256, K3_SMEM, st[1]>>>(hb2, out, chunk);

    // join
    cudaEventRecord(evJoin0, st[0]);
    cudaEventRecord(evJoin1, st[1]);
    cudaStreamWaitEvent(0, evJoin0, 0);
    cudaStreamWaitEvent(0, evJoin1, 0);
}

// round 12
// speedup vs baseline: 1.2725x; 1.2725x over previous
#include <cuda_runtime.h>
#include <cuda_fp16.h>
#include <cstdint>

typedef unsigned long long ull;

#define BMAX 32768

// ---------------- scratch (static device globals: no allocation) ----------------
__device__ __align__(16) float g_rot[18 * 8];
__device__ __align__(16) __half g_af[(size_t)BMAX * 128];  // A (activations) fp16
__device__ __align__(16) __half g_bh[1296 * 128];          // w2^T fp16 [N,K]
__device__ __align__(16) __half g_w1p[32 * 32 * 4 * 8];    // enc_w1 packed frags hi/lo

// ---------------- f32x2 packed helpers ----------------
__device__ __forceinline__ ull f2pack(float a, float b) {
    ull r;
    asm("mov.b64 %0, {%1, %2};" : "=l"(r) : "r"(__float_as_uint(a)), "r"(__float_as_uint(b)));
    return r;
}
__device__ __forceinline__ void f2unpack(ull v, float& a, float& b) {
    unsigned int lo, hi;
    asm("mov.b64 {%0, %1}, %2;" : "=r"(lo), "=r"(hi) : "l"(v));
    a = __uint_as_float(lo); b = __uint_as_float(hi);
}
__device__ __forceinline__ ull ffma2(ull a, ull b, ull c) {
    ull d;
    asm("fma.rn.f32x2 %0, %1, %2, %3;" : "=l"(d) : "l"(a), "l"(b), "l"(c));
    return d;
}
__device__ __forceinline__ ull fmul2(ull a, ull b) {
    ull d;
    asm("mul.rn.f32x2 %0, %1, %2;" : "=l"(d) : "l"(a), "l"(b));
    return d;
}

// ---------------- mma/ldmatrix helpers ----------------
__device__ __forceinline__ uint32_t smem_u32(const void* p) {
    uint32_t a;
    asm("{ .reg .u64 t; cvta.to.shared.u64 t, %1; cvt.u32.u64 %0, t; }" : "=r"(a) : "l"(p));
    return a;
}
__device__ __forceinline__ void ldsm4(uint32_t& r0, uint32_t& r1, uint32_t& r2, uint32_t& r3,
                                      uint32_t a) {
    asm volatile("ldmatrix.sync.aligned.m8n8.x4.shared.b16 {%0,%1,%2,%3}, [%4];"
                 : "=r"(r0), "=r"(r1), "=r"(r2), "=r"(r3) : "r"(a));
}
__device__ __forceinline__ void mma16816(float* d, uint32_t a0, uint32_t a1, uint32_t a2,
                                         uint32_t a3, uint32_t b0, uint32_t b1) {
    asm volatile(
        "mma.sync.aligned.m16n8k16.row.col.f32.f16.f16.f32 "
        "{%0,%1,%2,%3}, {%4,%5,%6,%7}, {%8,%9}, {%0,%1,%2,%3};"
        : "+f"(d[0]), "+f"(d[1]), "+f"(d[2]), "+f"(d[3])
        : "r"(a0), "r"(a1), "r"(a2), "r"(a3), "r"(b0), "r"(b1));
}
__device__ __forceinline__ uint32_t smaddr(uint32_t base, int row, int c) {
    return base + row * 256 + (((uint32_t)(c ^ (row & 7))) << 4);
}
__device__ __forceinline__ uint32_t h2pack(float a, float b) {
    __half2 h = __floats2half2_rn(a, b);
    return *(uint32_t*)&h;
}

// ---------------- K0: precompute Rot matrices ----------------
__global__ void k0_rot(const float* __restrict__ qw) {
    int t = threadIdx.x;
    if (t >= 18) return;
    float phi = qw[t * 3 + 0], th = qw[t * 3 + 1], om = qw[t * 3 + 2];
    float c = cosf(th * 0.5f), s = sinf(th * 0.5f);
    float ap = -(phi + om) * 0.5f, am = -(phi - om) * 0.5f;
    float sp, cp, sm, cm;
    sincosf(ap, &sp, &cp);
    sincosf(am, &sm, &cm);
    float* r = g_rot + t * 8;
    r[0] = cp * c;  r[1] = sp * c;
    r[2] = -cm * s; r[3] = sm * s;
    r[4] = cm * s;  r[5] = sm * s;
    r[6] = cp * c;  r[7] = -sp * c;
}

// ---------------- K0b: transpose head_w2 [128,1296] -> fp16 [1296,128] ----------------
__global__ void k_w2split(const float* __restrict__ w2) {
    int i = blockIdx.x * blockDim.x + threadIdx.x;
    if (i >= 1296 * 128) return;
    int n = i >> 7, k = i & 127;
    g_bh[i] = __float2half_rn(w2[k * 1296 + n]);
}

// ---------------- K0c: pack enc_w1 into mma-fragment order, fp16 hi/lo ----
__global__ void k_w1pack(const float* __restrict__ w1) {
    int i = blockIdx.x * blockDim.x + threadIdx.x;
    if (i >= 4096) return;
    int q = i & 3, ks = (i >> 2) & 31, n = i >> 7;
    int kc = ks * 16 + 4 * q;
    float v0 = w1[(kc + 0) * 32 + n];
    float v1 = w1[(kc + 1) * 32 + n];
    float v2 = w1[(kc + 2) * 32 + n];
    float v3 = w1[(kc + 3) * 32 + n];
    __half h[8];
    h[0] = __float2half_rn(v0); h[1] = __float2half_rn(v1);
    h[2] = __float2half_rn(v2); h[3] = __float2half_rn(v3);
    h[4] = __float2half_rn(v0 - __half2float(h[0]));
    h[5] = __float2half_rn(v1 - __half2float(h[1]));
    h[6] = __float2half_rn(v2 - __half2float(h[2]));
    h[7] = __float2half_rn(v3 - __half2float(h[3]));
    *(uint4*)(g_w1p + (size_t)i * 8) = *(uint4*)h;
}

// ---------------- circuit helpers ----------------
__device__ __forceinline__ float2 shflx(float2 v, int m) {
    float2 r;
    r.x = __shfl_xor_sync(0xffffffffu, v.x, m);
    r.y = __shfl_xor_sync(0xffffffffu, v.y, m);
    return r;
}
__device__ __forceinline__ float2 cmul(float2 a, float2 b) {
    return make_float2(a.x * b.x - a.y * b.y, a.x * b.y + a.y * b.x);
}
__device__ __forceinline__ float2 cmadd(float2 a, float2 b, float2 acc) {
    return make_float2(acc.x + a.x * b.x - a.y * b.y, acc.y + a.x * b.y + a.y * b.x);
}

// ---------------- K12: fused encoder (HMMA) + circuit, 32 samples/CTA ----------------
// phase 2: 4 samples/warp, 8 lanes/sample, 8 amps/lane (R10 layout, 64 regs)
__global__ __launch_bounds__(256)
void k12_fused(const float* __restrict__ x,
               const float* __restrict__ b1,
               const float* __restrict__ w2,
               const float* __restrict__ b2,
               const float* __restrict__ hw1,
               const float* __restrict__ hb1, int base) {
    __shared__ float red[2][3][32][16];
    __shared__ float sang[32][6];

    int tid = threadIdx.x, lane = tid & 31, wid = tid >> 5;

    // ======== phase 1: encoder ========
    {
        int tile = wid >> 2, tw = wid & 3;
        int m0 = base + blockIdx.x * 32 + tile * 16;
        int g = lane >> 2, q = lane & 3;
        const float* xr0 = x + (size_t)(m0 + g) * 512;
        const float* xr1 = x + (size_t)(m0 + g + 8) * 512;

        float acc[4][4];
#pragma unroll
        for (int nf = 0; nf < 4; nf++)
#pragma unroll
            for (int v = 0; v < 4; v++) acc[nf][v] = 0.f;

#pragma unroll
        for (int kk = 0; kk < 8; kk++) {
            int ks = tw * 8 + kk;
            int kc = ks * 16 + 4 * q;
            float4 v0 = *(const float4*)(xr0 + kc);
            float4 v1 = *(const float4*)(xr1 + kc);

            uint32_t ah0 = h2pack(v0.x, v0.y), ah1 = h2pack(v1.x, v1.y);
            uint32_t ah2 = h2pack(v0.z, v0.w), ah3 = h2pack(v1.z, v1.w);
            __half2 t0 = *(__half2*)&ah0, t1 = *(__half2*)&ah1;
            __half2 t2 = *(__half2*)&ah2, t3 = *(__half2*)&ah3;
            uint32_t al0 = h2pack(v0.x - __low2float(t0), v0.y - __high2float(t0));
            uint32_t al1 = h2pack(v1.x - __low2float(t1), v1.y - __high2float(t1));
            uint32_t al2 = h2pack(v0.z - __low2float(t2), v0.w - __high2float(t2));
            uint32_t al3 = h2pack(v1.z - __low2float(t3), v1.w - __high2float(t3));

#pragma unroll
            for (int nf = 0; nf < 4; nf++) {
                int n = nf * 8 + g;
                uint4 bv = *(const uint4*)(g_w1p + (size_t)(((n * 32 + ks) * 4 + q)) * 8);
                mma16816(acc[nf], ah0, ah1, ah2, ah3, bv.x, bv.y);
                mma16816(acc[nf], ah0, ah1, ah2, ah3, bv.z, bv.w);
                mma16816(acc[nf], al0, al1, al2, al3, bv.x, bv.y);
            }
        }

        if (tw) {
            float4* dst = (float4*)red[tile][tw - 1][lane];
#pragma unroll
            for (int nf = 0; nf < 4; nf++) dst[nf] = *(float4*)acc[nf];
        }
        __syncthreads();

        if (tw == 0) {
#pragma unroll
            for (int w = 0; w < 3; w++) {
                const float* src = red[tile][w][lane];
#pragma unroll
                for (int nf = 0; nf < 4; nf++)
#pragma unroll
                    for (int v = 0; v < 4; v++) acc[nf][v] += src[nf * 4 + v];
            }

            float pr0[6], pr1[6];
#pragma unroll
            for (int i = 0; i < 6; i++) { pr0[i] = 0.f; pr1[i] = 0.f; }

#pragma unroll
            for (int nf = 0; nf < 4; nf++) {
                int c0 = nf * 8 + 2 * q;
                float bb0 = b1[c0], bb1 = b1[c0 + 1];
                float h00 = tanhf(acc[nf][0] + bb0);
                float h01 = tanhf(acc[nf][1] + bb1);
                float h10 = tanhf(acc[nf][2] + bb0);
                float h11 = tanhf(acc[nf][3] + bb1);
#pragma unroll
                for (int i = 0; i < 6; i++) {
                    float w0 = w2[c0 * 6 + i], w1v = w2[(c0 + 1) * 6 + i];
                    pr0[i] += h00 * w0 + h01 * w1v;
                    pr1[i] += h10 * w0 + h11 * w1v;
                }
            }
#pragma unroll
            for (int m = 1; m <= 2; m <<= 1) {
#pragma unroll
                for (int i = 0; i < 6; i++) {
                    pr0[i] += __shfl_xor_sync(0xffffffffu, pr0[i], m);
                    pr1[i] += __shfl_xor_sync(0xffffffffu, pr1[i], m);
                }
            }
            if (q == 0) {
#pragma unroll
                for (int i = 0; i < 6; i++) {
                    sang[tile * 16 + g][i] = pr0[i] + b2[i];
                    sang[tile * 16 + g + 8][i] = pr1[i] + b2[i];
                }
            }
        }
    }
    __syncthreads();

    // ======== phase 2: circuit (4 samples/warp, 8 lanes/sample) ========
    int l3 = lane & 7;
    int ls = wid * 4 + (lane >> 3);
    int s = base + blockIdx.x * 32 + ls;

    float cs[6], sn[6];
#pragma unroll
    for (int q = 0; q < 6; q++) {
        float a = sang[ls][q];
        __sincosf(0.5f * a, &sn[q], &cs[q]);
    }

    float2 A[8];
#pragma unroll
    for (int j = 0; j < 8; j++) A[j] = make_float2(0.f, 0.f);
    if (l3 == 0) A[0].x = 1.f;

#pragma unroll
    for (int L = 0; L < 3; L++) {
#pragma unroll
        for (int q = 0; q < 6; q++) {
            const ull* up = (const ull*)(g_rot + (L * 6 + q) * 8);
            ull u01 = up[0], u23 = up[1], u45 = up[2], u67 = up[3];
            float c = cs[q], s2 = sn[q];
            ull cp = f2pack(c, c), sp = f2pack(s2, s2), sn2 = f2pack(-s2, -s2);
            float2 f00, f01, f10, f11;
            f2unpack(ffma2(u23, sp, fmul2(u01, cp)), f00.x, f00.y);
            f2unpack(ffma2(u01, sn2, fmul2(u23, cp)), f01.x, f01.y);
            f2unpack(ffma2(u67, sp, fmul2(u45, cp)), f10.x, f10.y);
            f2unpack(ffma2(u45, sn2, fmul2(u67, cp)), f11.x, f11.y);

            if (q <= 2) {
                int m = 4 >> q;
                bool hi = (l3 & m) != 0;
                float2 ua = hi ? f11 : f00;
                float2 ub = hi ? f10 : f01;
#pragma unroll
                for (int j = 0; j < 8; j++) {
                    float2 P = shflx(A[j], m);
                    A[j] = cmadd(ub, P, cmul(ua, A[j]));
                }
            } else {
                int lb = 5 - q;
                int st = 1 << lb;
#pragma unroll
                for (int i0 = 0; i0 < 8; i0++) {
                    if (i0 & st) continue;
                    int i1 = i0 | st;
                    float2 n0 = cmadd(f01, A[i1], cmul(f00, A[i0]));
                    float2 n1 = cmadd(f11, A[i1], cmul(f10, A[i0]));
                    A[i0] = n0; A[i1] = n1;
                }
            }
        }
        // CNOT ladder
        {
#pragma unroll
            for (int j = 0; j < 8; j++) {
                float2 P = shflx(A[j], 2);
                if (l3 & 4) A[j] = P;
            }
        }
        if (l3 & 1) {
#pragma unroll
            for (int j = 0; j < 4; j++) { float2 t = A[j]; A[j] = A[j + 4]; A[j + 4] = t; }
        }
        { float2 t = A[2]; A[2] = A[3]; A[3] = t; }
        { float2 t = A[6]; A[6] = A[7]; A[7] = t; }
        {
#pragma unroll
            for (int j = 0; j < 8; j++) {
                float2 P = shflx(A[j], 1);
                if (l3 & 2) A[j] = P;
            }
        }
        { float2 t = A[4]; A[4] = A[6]; A[6] = t; }
        { float2 t = A[5]; A[5] = A[7]; A[7] = t; }
        {
            A[1] = shflx(A[1], 4);
            A[3] = shflx(A[3], 4);
            A[5] = shflx(A[5], 4);
            A[7] = shflx(A[7], 4);
        }
    }

    float p[8];
#pragma unroll
    for (int j = 0; j < 8; j++) p[j] = A[j].x * A[j].x + A[j].y * A[j].y;
    float sum = (p[0] + p[1]) + (p[2] + p[3]) + (p[4] + p[5]) + (p[6] + p[7]);
    float z[6];
    z[0] = (l3 & 4) ? -sum : sum;
    z[1] = (l3 & 2) ? -sum : sum;
    z[2] = (l3 & 1) ? -sum : sum;
    z[3] = sum - 2.f * ((p[4] + p[5]) + (p[6] + p[7]));
    z[4] = sum - 2.f * ((p[2] + p[3]) + (p[6] + p[7]));
    z[5] = sum - 2.f * ((p[1] + p[3]) + (p[5] + p[7]));
#pragma unroll
    for (int off = 4; off; off >>= 1) {
#pragma unroll
        for (int q = 0; q < 6; q++) z[q] += __shfl_xor_sync(0xffffffffu, z[q], off);
    }

    __half hv[16];
#pragma unroll
    for (int u = 0; u < 16; u++) {
        int j = l3 * 16 + u;
        float a = hb1[j];
#pragma unroll
        for (int i = 0; i < 6; i++) a += z[i] * hw1[i * 128 + j];
        hv[u] = __float2half_rn(fmaxf(a, 0.f));
    }
    uint4* dst = (uint4*)(g_af + (size_t)s * 128 + l3 * 16);
    dst[0] = *(uint4*)&hv[0];
    dst[1] = *(uint4*)&hv[8];
}

// ---------------- K3: HMMA fp16 GEMM  out = A[B,128] @ w2[128,1296] + b2 ----
#define K3_SMEM (32768 + 36864)

__global__ __launch_bounds__(256, 2)
void k3_mma(const float* __restrict__ b2, float* __restrict__ out, int base) {
    extern __shared__ char sm3[];
    __half* sA  = (__half*)sm3;            // 128 x 128
    __half* sBh = (__half*)(sm3 + 32768);  // 144 x 128

    int tid = threadIdx.x, lane = tid & 31, wid = tid >> 5;
    int n0 = blockIdx.x * 144;
    int m0 = base + blockIdx.y * 128;

    const uint4* gA = (const uint4*)g_af + (size_t)m0 * 16;
    uint4* dA = (uint4*)sA;
#pragma unroll
    for (int it = 0; it < 8; it++) {
        int i = it * 256 + tid;
        int r = i >> 4, c = i & 15;
        dA[r * 16 + (c ^ (r & 7))] = gA[i];
    }
    const uint4* gBh = (const uint4*)g_bh + (size_t)n0 * 16;
    uint4* dBh = (uint4*)sBh;
#pragma unroll
    for (int it = 0; it < 9; it++) {
        int i = it * 256 + tid;
        int r = i >> 4, c = i & 15;
        dBh[r * 16 + (c ^ (r & 7))] = gBh[i];
    }
    __syncthreads();

    uint32_t sAb = smem_u32(sA), sBhb = smem_u32(sBh);
    int la = lane & 7, hb = (lane >> 3) & 1, hc = lane >> 4;
    int arow = wid * 16 + la + (hb << 3);
    int brow = la + (hb << 3);

    float acc[18][4];
#pragma unroll
    for (int j = 0; j < 18; j++)
#pragma unroll
        for (int v = 0; v < 4; v++) acc[j][v] = 0.f;

#pragma unroll
    for (int ks = 0; ks < 8; ks++) {
        int ca = 2 * ks + hc;
        uint32_t a0, a1, a2, a3;
        ldsm4(a0, a1, a2, a3, smaddr(sAb, arow, ca));

#pragma unroll
        for (int p = 0; p < 9; p++) {
            uint32_t r0, r1, r2, r3;
            ldsm4(r0, r1, r2, r3, smaddr(sBhb, p * 16 + brow, ca));
            mma16816(acc[2 * p],     a0, a1, a2, a3, r0, r2);
            mma16816(acc[2 * p + 1], a0, a1, a2, a3, r1, r3);
        }
    }

    int orow0 = m0 + wid * 16 + (lane >> 2);
    float* op = out + (size_t)orow0 * 1296 + n0 + 2 * (lane & 3);
    const float* bp = b2 + n0 + 2 * (lane & 3);
#pragma unroll
    for (int j = 0; j < 18; j++) {
        float2 bias = *(const float2*)(bp + 8 * j);
        float2 v0 = make_float2(acc[j][0] + bias.x, acc[j][1] + bias.y);
        float2 v1 = make_float2(acc[j][2] + bias.x, acc[j][3] + bias.y);
        __stcs((float2*)(op + 8 * j), v0);
        __stcs((float2*)(op + 8 * j + 8 * 1296), v1);
    }
}

// ---------------- launch: R10 layout + overlapped prep ----------------
extern "C" void kernel_launch(void* const* d_in, const int* in_sizes, int n_in,
                              void* d_out, int out_size) {
    const float* x   = (const float*)d_in[0];
    const float* ew1 = (const float*)d_in[1];
    const float* eb1 = (const float*)d_in[2];
    const float* ew2 = (const float*)d_in[3];
    const float* eb2 = (const float*)d_in[4];
    const float* qw  = (const float*)d_in[5];
    const float* hw1 = (const float*)d_in[6];
    const float* hb1 = (const float*)d_in[7];
    const float* hw2 = (const float*)d_in[8];
    const float* hb2 = (const float*)d_in[9];
    float* out = (float*)d_out;

    int B = in_sizes[0] / 512;

    static bool inited = false;
    static cudaStream_t st[2];
    static cudaEvent_t evFork, evW2, evJoin0, evJoin1;
    if (!inited) {
        cudaStreamCreateWithFlags(&st[0], cudaStreamNonBlocking);
        cudaStreamCreateWithFlags(&st[1], cudaStreamNonBlocking);
        cudaEventCreateWithFlags(&evFork, cudaEventDisableTiming);
        cudaEventCreateWithFlags(&evW2, cudaEventDisableTiming);
        cudaEventCreateWithFlags(&evJoin0, cudaEventDisableTiming);
        cudaEventCreateWithFlags(&evJoin1, cudaEventDisableTiming);
        cudaFuncSetAttribute(k3_mma, cudaFuncAttributeMaxDynamicSharedMemorySize, K3_SMEM);
        inited = true;
    }

    // prep needed by k12 (tiny) on the capture stream
    k0_rot<<<1, 32>>>(qw);
    k_w1pack<<<16, 256>>>(ew1);

    // fork
    cudaEventRecord(evFork, 0);
    cudaStreamWaitEvent(st[0], evFork, 0);
    cudaStreamWaitEvent(st[1], evFork, 0);

    int chunk = B / 2;  // 16384

    // k12 on both streams immediately (R10 layout)
    k12_fused<<<chunk / 32, 256, 0, st[0]>>>(x, eb1, ew2, eb2, hw1, hb1, 0);
    k12_fused<<<chunk / 32, 256, 0, st[1]>>>(x, eb1, ew2, eb2, hw1, hb1, chunk);

    // w2 transpose (needed only by k3) runs concurrently on the default stream
    k_w2split<<<(1296 * 128 + 255) / 256, 256>>>(hw2);
    cudaEventRecord(evW2, 0);
    cudaStreamWaitEvent(st[0], evW2, 0);
    cudaStreamWaitEvent(st[1], evW2, 0);

    dim3 g3(9, chunk / 128);
    k3_mma<<<g3, 256, K3_SMEM, st[0]>>>(hb2, out, 0);
    k3_mma<<<g3, 256, K3_SMEM, st[1]>>>(hb2, out, chunk);

    // join
    cudaEventRecord(evJoin0, st[0]);
    cudaEventRecord(evJoin1, st[1]);
    cudaStreamWaitEvent(0, evJoin0, 0);
    cudaStreamWaitEvent(0, evJoin1, 0);
}